// round 6
// baseline (speedup 1.0000x reference)
#include <cuda_runtime.h>
#include <cuda_bf16.h>
#include <cuda_fp16.h>
#include <math.h>
#include <stdint.h>

#define NN 100000      // nodes
#define NE 1600000     // edges
#define FD 128         // feature dim (H*D)
#define NH 4           // heads
#define NEG 0.2f       // leaky relu slope

#define SCAN_B 1024
#define SCAN_NBLK ((NN + SCAN_B - 1) / SCAN_B)   // 98

// ---------------- scratch (device globals; no allocation anywhere) -----------
__device__ __half g_f16[NN * FD]; // f = h @ W, fp16 (agg gather payload)
__device__ float g_h  [NN * FD];   // layer output buffer
__device__ float g_el [NN * NH];
__device__ float g_er [NN * NH];
__device__ int   g_deg   [NN];
__device__ int   g_cursor[NN];
__device__ int   g_off   [NN + 1];
__device__ int   g_bsum  [SCAN_NBLK];
__device__ int   g_srcs  [NE];     // src ids grouped by dst (CSR adjacency)
__device__ __nv_bfloat16 g_wt_hi[3][FD * FD];  // W^T split-high, [n][k] (K-major)
__device__ __nv_bfloat16 g_wt_lo[3][FD * FD];  // W^T split-low

// ============================ helpers ========================================
__device__ __forceinline__ uint32_t smem_u32(const void* p) {
    uint32_t a;
    asm("{ .reg .u64 t; cvta.to.shared.u64 t, %1; cvt.u32.u64 %0, t; }"
        : "=r"(a) : "l"(p));
    return a;
}

__device__ __forceinline__ void ldsm_x4(uint32_t* r, uint32_t addr) {
    asm volatile("ldmatrix.sync.aligned.m8n8.x4.shared.b16 {%0,%1,%2,%3}, [%4];"
                 : "=r"(r[0]), "=r"(r[1]), "=r"(r[2]), "=r"(r[3]) : "r"(addr));
}

#define MMA16816(d, a, b0v, b1v) \
    asm volatile("mma.sync.aligned.m16n8k16.row.col.f32.bf16.bf16.f32 " \
                 "{%0,%1,%2,%3}, {%4,%5,%6,%7}, {%8,%9}, {%0,%1,%2,%3};" \
                 : "+f"((d)[0]), "+f"((d)[1]), "+f"((d)[2]), "+f"((d)[3]) \
                 : "r"((a)[0]), "r"((a)[1]), "r"((a)[2]), "r"((a)[3]), \
                   "r"(b0v), "r"(b1v))

// Swizzled [rows x 128 bf16] tile: 256B/row; 16B chunk c at (c ^ (row&7)).
__device__ __forceinline__ uint32_t tile_addr(uint32_t base, int row, int chunk) {
    return base + (uint32_t)row * 256u + (uint32_t)((chunk ^ (row & 7)) << 4);
}

// ---------------- setup: W^T hi/lo splits for all 3 layers + CSR zero --------
__global__ void setup_kernel(const float* __restrict__ W0,
                             const float* __restrict__ W1,
                             const float* __restrict__ W2) {
    int t = blockIdx.x * blockDim.x + threadIdx.x;
    if (t < 3 * FD * FD) {
        int L = t / (FD * FD);
        int e = t % (FD * FD);
        int n = e >> 7, k = e & 127;
        const float* W = (L == 0) ? W0 : (L == 1) ? W1 : W2;
        float w = W[k * FD + n];
        __nv_bfloat16 hi = __float2bfloat16(w);
        __nv_bfloat16 lo = __float2bfloat16(w - __bfloat162float(hi));
        g_wt_hi[L][e] = hi;
        g_wt_lo[L][e] = lo;
    }
    if (t < NN) { g_deg[t] = 0; g_cursor[t] = 0; }
}

// ---------------- split-bf16 tensor GEMM + fused attention logits ------------
// One CTA per 64 rows; f = A @ W as Ah*Wh + Al*Wh + Ah*Wl (fp32 accum).
// 8 warps: wm=wid>>1 (16-row stripe), wn=wid&1 (64-col stripe = heads 2wn,2wn+1).
#define SM_AHI  0
#define SM_ALO  16384
#define SM_BHI  32768
#define SM_BLO  65536
#define SM_ATTN 98304                        // al[128], ar[128] floats
#define SM_TOTAL (SM_ATTN + 1024)

__global__ void __launch_bounds__(256, 2)
gemm_bf16_kernel(const float* __restrict__ inOpt,
                 const float* __restrict__ al,
                 const float* __restrict__ ar, int L) {
    extern __shared__ char smem[];
    const float* A = inOpt ? inOpt : g_h;
    uint32_t sb  = smem_u32(smem);
    int tid  = threadIdx.x;
    int wid  = tid >> 5;
    int lane = tid & 31;
    int wm   = wid >> 1;
    int wn   = wid & 1;
    int row0 = blockIdx.x * 64;

    // al/ar into smem
    if (tid < 128) {
        *(float*)(smem + SM_ATTN + tid * 4)       = al[tid];
        *(float*)(smem + SM_ATTN + 512 + tid * 4) = ar[tid];
    }

    // ---- load + split-convert A tile: 64 rows x 128 fp32 -> bf16 hi/lo ----
#pragma unroll
    for (int i = 0; i < 8; ++i) {
        int idx = tid + i * 256;            // 0..2047
        int r   = idx >> 5;                 // row 0..63
        int c4  = idx & 31;                 // float4 index in row
        int grow = row0 + r;
        float4 v = make_float4(0.f, 0.f, 0.f, 0.f);
        if (grow < NN) v = reinterpret_cast<const float4*>(A)[grow * 32 + c4];
        __nv_bfloat16 h0 = __float2bfloat16(v.x), h1 = __float2bfloat16(v.y);
        __nv_bfloat16 h2 = __float2bfloat16(v.z), h3 = __float2bfloat16(v.w);
        __nv_bfloat16 l0 = __float2bfloat16(v.x - __bfloat162float(h0));
        __nv_bfloat16 l1 = __float2bfloat16(v.y - __bfloat162float(h1));
        __nv_bfloat16 l2 = __float2bfloat16(v.z - __bfloat162float(h2));
        __nv_bfloat16 l3 = __float2bfloat16(v.w - __bfloat162float(h3));
        uint32_t off = (uint32_t)r * 256u + (uint32_t)((((c4 >> 1) ^ (r & 7)) << 4) | ((c4 & 1) << 3));
        *(uint2*)(smem + SM_AHI + off) = make_uint2(
            (uint32_t)__bfloat16_as_ushort(h0) | ((uint32_t)__bfloat16_as_ushort(h1) << 16),
            (uint32_t)__bfloat16_as_ushort(h2) | ((uint32_t)__bfloat16_as_ushort(h3) << 16));
        *(uint2*)(smem + SM_ALO + off) = make_uint2(
            (uint32_t)__bfloat16_as_ushort(l0) | ((uint32_t)__bfloat16_as_ushort(l1) << 16),
            (uint32_t)__bfloat16_as_ushort(l2) | ((uint32_t)__bfloat16_as_ushort(l3) << 16));
    }
    // ---- load B tiles (W^T hi/lo, already bf16, [n][k]) ----
#pragma unroll
    for (int i = 0; i < 16; ++i) {
        int idx = tid + i * 256;            // 0..4095
        int r   = idx >> 5;                 // n row 0..127
        int c4  = idx & 31;                 // uint2 (4 bf16) index in k
        uint2 vh = reinterpret_cast<const uint2*>(g_wt_hi[L])[r * 32 + c4];
        uint2 vl = reinterpret_cast<const uint2*>(g_wt_lo[L])[r * 32 + c4];
        uint32_t off = (uint32_t)r * 256u + (uint32_t)((((c4 >> 1) ^ (r & 7)) << 4) | ((c4 & 1) << 3));
        *(uint2*)(smem + SM_BHI + off) = vh;
        *(uint2*)(smem + SM_BLO + off) = vl;
    }
    __syncthreads();

    // ---- mainloop: 3 split passes x 8 k16-steps, 8 mma each ----
    float acc[8][4];
#pragma unroll
    for (int nf = 0; nf < 8; ++nf)
#pragma unroll
        for (int j = 0; j < 4; ++j) acc[nf][j] = 0.f;

    const int ar16 = (lane & 15);
    const int chi  = (lane >> 4);

#pragma unroll
    for (int pass = 0; pass < 3; ++pass) {
        uint32_t abase = sb + ((pass == 1) ? SM_ALO : SM_AHI);
        uint32_t bbase = sb + ((pass == 2) ? SM_BLO : SM_BHI);
#pragma unroll
        for (int kk = 0; kk < 8; ++kk) {
            int chunk = 2 * kk + chi;
            uint32_t a[4];
            ldsm_x4(a, tile_addr(abase, wm * 16 + ar16, chunk));
            uint32_t b[16];
#pragma unroll
            for (int bp = 0; bp < 4; ++bp)
                ldsm_x4(b + bp * 4, tile_addr(bbase, wn * 64 + bp * 16 + ar16, chunk));
#pragma unroll
            for (int nf = 0; nf < 8; ++nf) {
                uint32_t b0v = b[(nf >> 1) * 4 + (nf & 1)];
                uint32_t b1v = b[(nf >> 1) * 4 + 2 + (nf & 1)];
                MMA16816(acc[nf], a, b0v, b1v);
            }
        }
    }

    // ---- epilogue: store f (fp16), compute el/er from fp32 accumulators ----
    const float* s_al = (const float*)(smem + SM_ATTN);
    const float* s_ar = (const float*)(smem + SM_ATTN + 512);
    uint32_t* F16 = reinterpret_cast<uint32_t*>(g_f16);   // half2 view

    int r_lo = row0 + wm * 16 + (lane >> 2);
    int r_hi = r_lo + 8;
    float elL[2] = {0.f, 0.f}, elH[2] = {0.f, 0.f};
    float erL[2] = {0.f, 0.f}, erH[2] = {0.f, 0.f};
#pragma unroll
    for (int nf = 0; nf < 8; ++nf) {
        int col = wn * 64 + nf * 8 + (lane & 3) * 2;
        int h   = nf >> 2;
        float a0v = s_al[col], a1v = s_al[col + 1];
        float r0v = s_ar[col], r1v = s_ar[col + 1];
        float* c = acc[nf];
        elL[h] += c[0] * a0v + c[1] * a1v;
        erL[h] += c[0] * r0v + c[1] * r1v;
        elH[h] += c[2] * a0v + c[3] * a1v;
        erH[h] += c[2] * r0v + c[3] * r1v;
        if (r_lo < NN) {
            __half2 p = __floats2half2_rn(c[0], c[1]);
            F16[(r_lo * FD + col) >> 1] = *(uint32_t*)&p;
        }
        if (r_hi < NN) {
            __half2 p = __floats2half2_rn(c[2], c[3]);
            F16[(r_hi * FD + col) >> 1] = *(uint32_t*)&p;
        }
    }
    // reduce over the 4 lanes sharing each row
#pragma unroll
    for (int h = 0; h < 2; ++h) {
        elL[h] += __shfl_xor_sync(0xffffffffu, elL[h], 1);
        elL[h] += __shfl_xor_sync(0xffffffffu, elL[h], 2);
        elH[h] += __shfl_xor_sync(0xffffffffu, elH[h], 1);
        elH[h] += __shfl_xor_sync(0xffffffffu, elH[h], 2);
        erL[h] += __shfl_xor_sync(0xffffffffu, erL[h], 1);
        erL[h] += __shfl_xor_sync(0xffffffffu, erL[h], 2);
        erH[h] += __shfl_xor_sync(0xffffffffu, erH[h], 1);
        erH[h] += __shfl_xor_sync(0xffffffffu, erH[h], 2);
    }
    if ((lane & 3) == 0) {
#pragma unroll
        for (int h = 0; h < 2; ++h) {
            int gh = 2 * wn + h;
            if (r_lo < NN) { g_el[r_lo * NH + gh] = elL[h]; g_er[r_lo * NH + gh] = erL[h]; }
            if (r_hi < NN) { g_el[r_hi * NH + gh] = elH[h]; g_er[r_hi * NH + gh] = erH[h]; }
        }
    }
}

// ---------------- CSR build (once per launch) --------------------------------
__global__ void csr_hist_kernel(const int* __restrict__ dst) {
    int e = blockIdx.x * blockDim.x + threadIdx.x;
    if (e < NE) atomicAdd(&g_deg[dst[e]], 1);
}

__global__ void csr_scan1_kernel() {
    __shared__ int sd[SCAN_B];
    int t = threadIdx.x;
    int i = blockIdx.x * SCAN_B + t;
    int v = (i < NN) ? g_deg[i] : 0;
    sd[t] = v;
    __syncthreads();
#pragma unroll
    for (int off = 1; off < SCAN_B; off <<= 1) {
        int tv = (t >= off) ? sd[t - off] : 0;
        __syncthreads();
        sd[t] += tv;
        __syncthreads();
    }
    if (i < NN) g_off[i + 1] = sd[t];
    if (t == SCAN_B - 1) g_bsum[blockIdx.x] = sd[t];
}

__global__ void csr_scan2_kernel() {
    __shared__ int sd[128];
    int t = threadIdx.x;
    sd[t] = (t < SCAN_NBLK) ? g_bsum[t] : 0;
    __syncthreads();
#pragma unroll
    for (int off = 1; off < 128; off <<= 1) {
        int tv = (t >= off) ? sd[t - off] : 0;
        __syncthreads();
        sd[t] += tv;
        __syncthreads();
    }
    if (t < SCAN_NBLK) g_bsum[t] = sd[t];
}

__global__ void csr_scan3_kernel() {
    int i = blockIdx.x * blockDim.x + threadIdx.x;
    if (i == 0) g_off[0] = 0;
    if (i < NN) {
        int b = i / SCAN_B;
        if (b > 0) g_off[i + 1] += g_bsum[b - 1];
    }
}

__global__ void csr_scatter_kernel(const int* __restrict__ src,
                                   const int* __restrict__ dst) {
    int e = blockIdx.x * blockDim.x + threadIdx.x;
    if (e >= NE) return;
    int v = dst[e];
    int p = g_off[v] + atomicAdd(&g_cursor[v], 1);
    g_srcs[p] = src[e];
}

// ---------------- fused edge softmax + aggregate + normalize + relu ----------
// one warp per dst node; lane l: head l/8, dims l*4..+3 (fp16 gather), unroll-2
__global__ void agg_kernel(float* __restrict__ outOpt) {
    float* out = outOpt ? outOpt : g_h;
    int gw   = (blockIdx.x * blockDim.x + threadIdx.x) >> 5;
    int lane = threadIdx.x & 31;
    if (gw >= NN) return;

    int beg = g_off[gw];
    int end = g_off[gw + 1];
    int h   = lane >> 3;
    float er_h = g_er[gw * NH + h];

    const uint2* F16 = reinterpret_cast<const uint2*>(g_f16);  // 4 halves/elem
    float4 acc0 = make_float4(0.f, 0.f, 0.f, 0.f);
    float4 acc1 = make_float4(0.f, 0.f, 0.f, 0.f);
    float  s0 = 0.f, s1 = 0.f;

    int p = beg;
    for (; p + 1 < end; p += 2) {
        int u0 = __ldg(&g_srcs[p]);
        int u1 = __ldg(&g_srcs[p + 1]);
        float e0 = __ldg(&g_el[u0 * NH + h]) + er_h;
        float e1 = __ldg(&g_el[u1 * NH + h]) + er_h;
        uint2 raw0 = F16[u0 * 32 + lane];
        uint2 raw1 = F16[u1 * 32 + lane];
        e0 = (e0 > 0.f) ? e0 : NEG * e0;
        e1 = (e1 > 0.f) ? e1 : NEG * e1;
        float ex0 = __expf(e0);
        float ex1 = __expf(e1);
        float2 a01 = __half22float2(*(const __half2*)&raw0.x);
        float2 a23 = __half22float2(*(const __half2*)&raw0.y);
        float2 b01 = __half22float2(*(const __half2*)&raw1.x);
        float2 b23 = __half22float2(*(const __half2*)&raw1.y);
        acc0.x += ex0 * a01.x; acc0.y += ex0 * a01.y;
        acc0.z += ex0 * a23.x; acc0.w += ex0 * a23.y;
        acc1.x += ex1 * b01.x; acc1.y += ex1 * b01.y;
        acc1.z += ex1 * b23.x; acc1.w += ex1 * b23.y;
        s0 += ex0; s1 += ex1;
    }
    if (p < end) {
        int u = __ldg(&g_srcs[p]);
        float e = __ldg(&g_el[u * NH + h]) + er_h;
        e = (e > 0.f) ? e : NEG * e;
        float ex = __expf(e);
        uint2 raw = F16[u * 32 + lane];
        float2 f01 = __half22float2(*(const __half2*)&raw.x);
        float2 f23 = __half22float2(*(const __half2*)&raw.y);
        acc0.x += ex * f01.x; acc0.y += ex * f01.y;
        acc0.z += ex * f23.x; acc0.w += ex * f23.y;
        s0 += ex;
    }

    float inv = 1.f / (s0 + s1 + 1e-9f);
    float4 o;
    o.x = fmaxf((acc0.x + acc1.x) * inv, 0.f);
    o.y = fmaxf((acc0.y + acc1.y) * inv, 0.f);
    o.z = fmaxf((acc0.z + acc1.z) * inv, 0.f);
    o.w = fmaxf((acc0.w + acc1.w) * inv, 0.f);
    reinterpret_cast<float4*>(out)[gw * 32 + lane] = o;
}

// ---------------- launch ------------------------------------------------------
extern "C" void kernel_launch(void* const* d_in, const int* in_sizes, int n_in,
                              void* d_out, int out_size) {
    const float* x   = (const float*)d_in[0];
    const int*   ei  = (const int*)d_in[1];
    const int*   src = ei;
    const int*   dst = ei + NE;
    const float* W[3]  = { (const float*)d_in[2], (const float*)d_in[5], (const float*)d_in[8]  };
    const float* al[3] = { (const float*)d_in[3], (const float*)d_in[6], (const float*)d_in[9]  };
    const float* ar[3] = { (const float*)d_in[4], (const float*)d_in[7], (const float*)d_in[10] };
    float* out = (float*)d_out;

    cudaFuncSetAttribute(gemm_bf16_kernel,
                         cudaFuncAttributeMaxDynamicSharedMemorySize, SM_TOTAL);

    const int gemm_blocks = (NN + 63) / 64;            // 1563
    const int node_warps  = (NN * 32 + 255) / 256;
    const int node_blocks = (NN + 255) / 256;
    const int edge_blocks = (NE + 255) / 256;
    const int setup_blocks = (NN + 255) / 256;         // covers 3*16384 too

    // launch idx:       0        1      2      3      4      5(gemm0: ncu -s 5)
    setup_kernel      <<<setup_blocks, 256>>>(W[0], W[1], W[2]);
    csr_hist_kernel   <<<edge_blocks, 256>>>(dst);
    csr_scan1_kernel  <<<SCAN_NBLK, SCAN_B>>>();
    csr_scan2_kernel  <<<1, 128>>>();
    csr_scan3_kernel  <<<node_blocks, 256>>>();
    gemm_bf16_kernel  <<<gemm_blocks, 256, SM_TOTAL>>>(x, al[0], ar[0], 0);
    csr_scatter_kernel<<<edge_blocks, 256>>>(src, dst);
    agg_kernel        <<<node_warps, 256>>>(nullptr);

    gemm_bf16_kernel  <<<gemm_blocks, 256, SM_TOTAL>>>(nullptr, al[1], ar[1], 1);
    agg_kernel        <<<node_warps, 256>>>(nullptr);
    gemm_bf16_kernel  <<<gemm_blocks, 256, SM_TOTAL>>>(nullptr, al[2], ar[2], 2);
    agg_kernel        <<<node_warps, 256>>>(out);
}

// round 8
// speedup vs baseline: 1.1629x; 1.1629x over previous
#include <cuda_runtime.h>
#include <cuda_bf16.h>
#include <cuda_fp16.h>
#include <math.h>
#include <stdint.h>

#define NN 100000      // nodes
#define NE 1600000     // edges
#define FD 128         // feature dim (H*D)
#define NH 4           // heads
#define NEG 0.2f       // leaky relu slope

#define SCAN_B 1024
#define SCAN_NBLK ((NN + SCAN_B - 1) / SCAN_B)   // 98

// ---------------- scratch (device globals; no allocation anywhere) -----------
__device__ __half g_f16[NN * FD]; // f = h @ W, fp16 (agg gather payload)
__device__ float g_h  [NN * FD];   // layer output buffer
__device__ float g_el [NN * NH];
__device__ float g_er [NN * NH];
__device__ int   g_deg   [NN];
__device__ int   g_cursor[NN];
__device__ int   g_off   [NN + 1];
__device__ int   g_bsum  [SCAN_NBLK];
__device__ int   g_srcs  [NE];     // src ids grouped by dst (CSR adjacency)
__device__ __nv_bfloat16 g_wt_hi[3][FD * FD];  // W^T split-high, [n][k] (K-major)
__device__ __nv_bfloat16 g_wt_lo[3][FD * FD];  // W^T split-low

// ============================ helpers ========================================
__device__ __forceinline__ uint32_t smem_u32(const void* p) {
    uint32_t a;
    asm("{ .reg .u64 t; cvta.to.shared.u64 t, %1; cvt.u32.u64 %0, t; }"
        : "=r"(a) : "l"(p));
    return a;
}

__device__ __forceinline__ void ldsm_x4(uint32_t* r, uint32_t addr) {
    asm volatile("ldmatrix.sync.aligned.m8n8.x4.shared.b16 {%0,%1,%2,%3}, [%4];"
                 : "=r"(r[0]), "=r"(r[1]), "=r"(r[2]), "=r"(r[3]) : "r"(addr));
}

#define MMA16816(d, a, b0v, b1v) \
    asm volatile("mma.sync.aligned.m16n8k16.row.col.f32.bf16.bf16.f32 " \
                 "{%0,%1,%2,%3}, {%4,%5,%6,%7}, {%8,%9}, {%0,%1,%2,%3};" \
                 : "+f"((d)[0]), "+f"((d)[1]), "+f"((d)[2]), "+f"((d)[3]) \
                 : "r"((a)[0]), "r"((a)[1]), "r"((a)[2]), "r"((a)[3]), \
                   "r"(b0v), "r"(b1v))

// Swizzled [128 rows x 128 bf16] tile: 256B/row; 16B chunk c at (c ^ (row&7)).
__device__ __forceinline__ uint32_t tile_addr(uint32_t base, int row, int chunk) {
    return base + (uint32_t)row * 256u + (uint32_t)((chunk ^ (row & 7)) << 4);
}

// ---------------- setup: W^T hi/lo splits for all 3 layers + CSR zero --------
__global__ void setup_kernel(const float* __restrict__ W0,
                             const float* __restrict__ W1,
                             const float* __restrict__ W2) {
    int t = blockIdx.x * blockDim.x + threadIdx.x;
    if (t < 3 * FD * FD) {
        int L = t / (FD * FD);
        int e = t % (FD * FD);
        int n = e >> 7, k = e & 127;
        const float* W = (L == 0) ? W0 : (L == 1) ? W1 : W2;
        float w = W[k * FD + n];
        __nv_bfloat16 hi = __float2bfloat16(w);
        __nv_bfloat16 lo = __float2bfloat16(w - __bfloat162float(hi));
        g_wt_hi[L][e] = hi;
        g_wt_lo[L][e] = lo;
    }
    if (t < NN) { g_deg[t] = 0; g_cursor[t] = 0; }
}

// ---------------- split-bf16 tensor GEMM + fused attention logits ------------
// One CTA per 128 rows; f = A @ W as Ah*Wh + Al*Wh + Ah*Wl (fp32 accum).
// 8 warps: wm=wid>>1 (32-row stripe), wn=wid&1 (64-col stripe = heads 2wn,2wn+1).
#define SM_AHI  0
#define SM_ALO  32768
#define SM_BHI  65536
#define SM_BLO  98304
#define SM_ATTN 131072                       // al[128], ar[128] floats
#define SM_TOTAL (SM_ATTN + 1024)

__global__ void __launch_bounds__(256, 1)
gemm_bf16_kernel(const float* __restrict__ inOpt,
                 const float* __restrict__ al,
                 const float* __restrict__ ar, int L) {
    extern __shared__ char smem[];
    const float* A = inOpt ? inOpt : g_h;
    uint32_t sb  = smem_u32(smem);
    int tid  = threadIdx.x;
    int wid  = tid >> 5;
    int lane = tid & 31;
    int wm   = wid >> 1;
    int wn   = wid & 1;
    int row0 = blockIdx.x * 128;

    // al/ar into smem
    if (tid < 128) {
        *(float*)(smem + SM_ATTN + tid * 4)       = al[tid];
        *(float*)(smem + SM_ATTN + 512 + tid * 4) = ar[tid];
    }

    // ---- load + split-convert A tile: 128 rows x 128 fp32 -> bf16 hi/lo ----
#pragma unroll
    for (int i = 0; i < 16; ++i) {
        int idx = tid + i * 256;            // 0..4095
        int r   = idx >> 5;                 // row 0..127
        int c4  = idx & 31;                 // float4 index in row
        int grow = row0 + r;
        float4 v = make_float4(0.f, 0.f, 0.f, 0.f);
        if (grow < NN) v = reinterpret_cast<const float4*>(A)[grow * 32 + c4];
        __nv_bfloat16 h0 = __float2bfloat16(v.x), h1 = __float2bfloat16(v.y);
        __nv_bfloat16 h2 = __float2bfloat16(v.z), h3 = __float2bfloat16(v.w);
        __nv_bfloat16 l0 = __float2bfloat16(v.x - __bfloat162float(h0));
        __nv_bfloat16 l1 = __float2bfloat16(v.y - __bfloat162float(h1));
        __nv_bfloat16 l2 = __float2bfloat16(v.z - __bfloat162float(h2));
        __nv_bfloat16 l3 = __float2bfloat16(v.w - __bfloat162float(h3));
        uint32_t off = (uint32_t)r * 256u + (uint32_t)((((c4 >> 1) ^ (r & 7)) << 4) | ((c4 & 1) << 3));
        *(uint2*)(smem + SM_AHI + off) = make_uint2(
            (uint32_t)__bfloat16_as_ushort(h0) | ((uint32_t)__bfloat16_as_ushort(h1) << 16),
            (uint32_t)__bfloat16_as_ushort(h2) | ((uint32_t)__bfloat16_as_ushort(h3) << 16));
        *(uint2*)(smem + SM_ALO + off) = make_uint2(
            (uint32_t)__bfloat16_as_ushort(l0) | ((uint32_t)__bfloat16_as_ushort(l1) << 16),
            (uint32_t)__bfloat16_as_ushort(l2) | ((uint32_t)__bfloat16_as_ushort(l3) << 16));
    }
    // ---- load B tiles (W^T hi/lo, already bf16, [n][k]) ----
#pragma unroll
    for (int i = 0; i < 16; ++i) {
        int idx = tid + i * 256;
        int r   = idx >> 5;                 // n row
        int c4  = idx & 31;                 // uint2 (4 bf16) index in k
        uint2 vh = reinterpret_cast<const uint2*>(g_wt_hi[L])[r * 32 + c4];
        uint2 vl = reinterpret_cast<const uint2*>(g_wt_lo[L])[r * 32 + c4];
        uint32_t off = (uint32_t)r * 256u + (uint32_t)((((c4 >> 1) ^ (r & 7)) << 4) | ((c4 & 1) << 3));
        *(uint2*)(smem + SM_BHI + off) = vh;
        *(uint2*)(smem + SM_BLO + off) = vl;
    }
    __syncthreads();

    // ---- mainloop: 3 split passes x 8 k16-steps, 16 mma each ----
    float acc[2][8][4];
#pragma unroll
    for (int mf = 0; mf < 2; ++mf)
#pragma unroll
        for (int nf = 0; nf < 8; ++nf)
#pragma unroll
            for (int j = 0; j < 4; ++j) acc[mf][nf][j] = 0.f;

    const int ar16 = (lane & 15);
    const int chi  = (lane >> 4);

#pragma unroll
    for (int pass = 0; pass < 3; ++pass) {
        uint32_t abase = sb + ((pass == 1) ? SM_ALO : SM_AHI);
        uint32_t bbase = sb + ((pass == 2) ? SM_BLO : SM_BHI);
#pragma unroll
        for (int kk = 0; kk < 8; ++kk) {
            int chunk = 2 * kk + chi;
            uint32_t a[8];
            ldsm_x4(a,     tile_addr(abase, wm * 32 + ar16,      chunk));
            ldsm_x4(a + 4, tile_addr(abase, wm * 32 + 16 + ar16, chunk));
            uint32_t b[16];
#pragma unroll
            for (int bp = 0; bp < 4; ++bp)
                ldsm_x4(b + bp * 4, tile_addr(bbase, wn * 64 + bp * 16 + ar16, chunk));
#pragma unroll
            for (int mf = 0; mf < 2; ++mf)
#pragma unroll
                for (int nf = 0; nf < 8; ++nf) {
                    uint32_t b0v = b[(nf >> 1) * 4 + (nf & 1)];
                    uint32_t b1v = b[(nf >> 1) * 4 + 2 + (nf & 1)];
                    MMA16816(acc[mf][nf], a + mf * 4, b0v, b1v);
                }
        }
    }

    // ---- epilogue: store f (fp16), compute el/er from fp32 accumulators ----
    const float* s_al = (const float*)(smem + SM_ATTN);
    const float* s_ar = (const float*)(smem + SM_ATTN + 512);
    uint32_t* F16 = reinterpret_cast<uint32_t*>(g_f16);   // half2 view

#pragma unroll
    for (int mf = 0; mf < 2; ++mf) {
        int r_lo = row0 + wm * 32 + mf * 16 + (lane >> 2);
        int r_hi = r_lo + 8;
        float elL[2] = {0.f, 0.f}, elH[2] = {0.f, 0.f};
        float erL[2] = {0.f, 0.f}, erH[2] = {0.f, 0.f};
#pragma unroll
        for (int nf = 0; nf < 8; ++nf) {
            int col = wn * 64 + nf * 8 + (lane & 3) * 2;
            int h   = nf >> 2;
            float a0v = s_al[col], a1v = s_al[col + 1];
            float r0v = s_ar[col], r1v = s_ar[col + 1];
            float* c = acc[mf][nf];
            elL[h] += c[0] * a0v + c[1] * a1v;
            erL[h] += c[0] * r0v + c[1] * r1v;
            elH[h] += c[2] * a0v + c[3] * a1v;
            erH[h] += c[2] * r0v + c[3] * r1v;
            if (r_lo < NN) {
                __half2 p = __floats2half2_rn(c[0], c[1]);
                F16[(r_lo * FD + col) >> 1] = *(uint32_t*)&p;
            }
            if (r_hi < NN) {
                __half2 p = __floats2half2_rn(c[2], c[3]);
                F16[(r_hi * FD + col) >> 1] = *(uint32_t*)&p;
            }
        }
        // reduce over the 4 lanes sharing each row
#pragma unroll
        for (int h = 0; h < 2; ++h) {
            elL[h] += __shfl_xor_sync(0xffffffffu, elL[h], 1);
            elL[h] += __shfl_xor_sync(0xffffffffu, elL[h], 2);
            elH[h] += __shfl_xor_sync(0xffffffffu, elH[h], 1);
            elH[h] += __shfl_xor_sync(0xffffffffu, elH[h], 2);
            erL[h] += __shfl_xor_sync(0xffffffffu, erL[h], 1);
            erL[h] += __shfl_xor_sync(0xffffffffu, erL[h], 2);
            erH[h] += __shfl_xor_sync(0xffffffffu, erH[h], 1);
            erH[h] += __shfl_xor_sync(0xffffffffu, erH[h], 2);
        }
        if ((lane & 3) == 0) {
#pragma unroll
            for (int h = 0; h < 2; ++h) {
                int gh = 2 * wn + h;
                if (r_lo < NN) { g_el[r_lo * NH + gh] = elL[h]; g_er[r_lo * NH + gh] = erL[h]; }
                if (r_hi < NN) { g_el[r_hi * NH + gh] = elH[h]; g_er[r_hi * NH + gh] = erH[h]; }
            }
        }
    }
}

// ---------------- CSR build (once per launch) --------------------------------
__global__ void csr_hist_kernel(const int* __restrict__ dst) {
    int e = blockIdx.x * blockDim.x + threadIdx.x;
    if (e < NE) atomicAdd(&g_deg[dst[e]], 1);
}

__global__ void csr_scan1_kernel() {
    __shared__ int sd[SCAN_B];
    int t = threadIdx.x;
    int i = blockIdx.x * SCAN_B + t;
    int v = (i < NN) ? g_deg[i] : 0;
    sd[t] = v;
    __syncthreads();
#pragma unroll
    for (int off = 1; off < SCAN_B; off <<= 1) {
        int tv = (t >= off) ? sd[t - off] : 0;
        __syncthreads();
        sd[t] += tv;
        __syncthreads();
    }
    if (i < NN) g_off[i + 1] = sd[t];
    if (t == SCAN_B - 1) g_bsum[blockIdx.x] = sd[t];
}

__global__ void csr_scan2_kernel() {
    __shared__ int sd[128];
    int t = threadIdx.x;
    sd[t] = (t < SCAN_NBLK) ? g_bsum[t] : 0;
    __syncthreads();
#pragma unroll
    for (int off = 1; off < 128; off <<= 1) {
        int tv = (t >= off) ? sd[t - off] : 0;
        __syncthreads();
        sd[t] += tv;
        __syncthreads();
    }
    if (t < SCAN_NBLK) g_bsum[t] = sd[t];
}

__global__ void csr_scan3_kernel() {
    int i = blockIdx.x * blockDim.x + threadIdx.x;
    if (i == 0) g_off[0] = 0;
    if (i < NN) {
        int b = i / SCAN_B;
        if (b > 0) g_off[i + 1] += g_bsum[b - 1];
    }
}

__global__ void csr_scatter_kernel(const int* __restrict__ src,
                                   const int* __restrict__ dst) {
    int e = blockIdx.x * blockDim.x + threadIdx.x;
    if (e >= NE) return;
    int v = dst[e];
    int p = g_off[v] + atomicAdd(&g_cursor[v], 1);
    g_srcs[p] = src[e];
}

// ---------------- fused edge softmax + aggregate + normalize + relu ----------
// one warp per dst node; lane l: head l/8, dims l*4..+3 (fp16 gather), unroll-2
__global__ void agg_kernel(float* __restrict__ outOpt) {
    float* out = outOpt ? outOpt : g_h;
    int gw   = (blockIdx.x * blockDim.x + threadIdx.x) >> 5;
    int lane = threadIdx.x & 31;
    if (gw >= NN) return;

    int beg = g_off[gw];
    int end = g_off[gw + 1];
    int h   = lane >> 3;
    float er_h = g_er[gw * NH + h];

    const uint2* F16 = reinterpret_cast<const uint2*>(g_f16);  // 4 halves/elem
    float4 acc0 = make_float4(0.f, 0.f, 0.f, 0.f);
    float4 acc1 = make_float4(0.f, 0.f, 0.f, 0.f);
    float  s0 = 0.f, s1 = 0.f;

    int p = beg;
    for (; p + 1 < end; p += 2) {
        int u0 = __ldg(&g_srcs[p]);
        int u1 = __ldg(&g_srcs[p + 1]);
        float e0 = __ldg(&g_el[u0 * NH + h]) + er_h;
        float e1 = __ldg(&g_el[u1 * NH + h]) + er_h;
        uint2 raw0 = F16[u0 * 32 + lane];
        uint2 raw1 = F16[u1 * 32 + lane];
        e0 = (e0 > 0.f) ? e0 : NEG * e0;
        e1 = (e1 > 0.f) ? e1 : NEG * e1;
        float ex0 = __expf(e0);
        float ex1 = __expf(e1);
        float2 a01 = __half22float2(*(const __half2*)&raw0.x);
        float2 a23 = __half22float2(*(const __half2*)&raw0.y);
        float2 b01 = __half22float2(*(const __half2*)&raw1.x);
        float2 b23 = __half22float2(*(const __half2*)&raw1.y);
        acc0.x += ex0 * a01.x; acc0.y += ex0 * a01.y;
        acc0.z += ex0 * a23.x; acc0.w += ex0 * a23.y;
        acc1.x += ex1 * b01.x; acc1.y += ex1 * b01.y;
        acc1.z += ex1 * b23.x; acc1.w += ex1 * b23.y;
        s0 += ex0; s1 += ex1;
    }
    if (p < end) {
        int u = __ldg(&g_srcs[p]);
        float e = __ldg(&g_el[u * NH + h]) + er_h;
        e = (e > 0.f) ? e : NEG * e;
        float ex = __expf(e);
        uint2 raw = F16[u * 32 + lane];
        float2 f01 = __half22float2(*(const __half2*)&raw.x);
        float2 f23 = __half22float2(*(const __half2*)&raw.y);
        acc0.x += ex * f01.x; acc0.y += ex * f01.y;
        acc0.z += ex * f23.x; acc0.w += ex * f23.y;
        s0 += ex;
    }

    float inv = 1.f / (s0 + s1 + 1e-9f);
    float4 o;
    o.x = fmaxf((acc0.x + acc1.x) * inv, 0.f);
    o.y = fmaxf((acc0.y + acc1.y) * inv, 0.f);
    o.z = fmaxf((acc0.z + acc1.z) * inv, 0.f);
    o.w = fmaxf((acc0.w + acc1.w) * inv, 0.f);
    reinterpret_cast<float4*>(out)[gw * 32 + lane] = o;
}

// ---------------- launch ------------------------------------------------------
extern "C" void kernel_launch(void* const* d_in, const int* in_sizes, int n_in,
                              void* d_out, int out_size) {
    const float* x   = (const float*)d_in[0];
    const int*   ei  = (const int*)d_in[1];
    const int*   src = ei;
    const int*   dst = ei + NE;
    const float* W[3]  = { (const float*)d_in[2], (const float*)d_in[5], (const float*)d_in[8]  };
    const float* al[3] = { (const float*)d_in[3], (const float*)d_in[6], (const float*)d_in[9]  };
    const float* ar[3] = { (const float*)d_in[4], (const float*)d_in[7], (const float*)d_in[10] };
    float* out = (float*)d_out;

    cudaFuncSetAttribute(gemm_bf16_kernel,
                         cudaFuncAttributeMaxDynamicSharedMemorySize, SM_TOTAL);

    const int gemm_blocks = (NN + 127) / 128;          // 782
    const int node_warps  = (NN * 32 + 255) / 256;
    const int node_blocks = (NN + 255) / 256;
    const int edge_blocks = (NE + 255) / 256;
    const int setup_blocks = (NN + 255) / 256;         // covers 3*16384 too

    // launch idx:       0        1      2      3 (<- ncu captures idx 3)
    setup_kernel      <<<setup_blocks, 256>>>(W[0], W[1], W[2]);
    csr_hist_kernel   <<<edge_blocks, 256>>>(dst);
    csr_scan1_kernel  <<<SCAN_NBLK, SCAN_B>>>();
    gemm_bf16_kernel  <<<gemm_blocks, 256, SM_TOTAL>>>(x, al[0], ar[0], 0);
    csr_scan2_kernel  <<<1, 128>>>();
    csr_scan3_kernel  <<<node_blocks, 256>>>();
    csr_scatter_kernel<<<edge_blocks, 256>>>(src, dst);
    agg_kernel        <<<node_warps, 256>>>(nullptr);

    gemm_bf16_kernel  <<<gemm_blocks, 256, SM_TOTAL>>>(nullptr, al[1], ar[1], 1);
    agg_kernel        <<<node_warps, 256>>>(nullptr);
    gemm_bf16_kernel  <<<gemm_blocks, 256, SM_TOTAL>>>(nullptr, al[2], ar[2], 2);
    agg_kernel        <<<node_warps, 256>>>(out);
}